// round 7
// baseline (speedup 1.0000x reference)
#include <cuda_runtime.h>

#define PAIRS 80
#define SEQ   2048
#define VD    768
#define HID   512
#define HID2  1024
#define NOUT  5
#define NCHUNK 32
#define ROWS_PER_CHUNK (SEQ / NCHUNK)   // 64
#define FWARPS 4                        // flash warps per block

// ---------------- scratch (static device globals; no allocs) ----------------
__device__ float g_X[PAIRS * HID2];     // concat: [:,0:512]=pooled_v, [:,512:1024]=q
__device__ float g_QQ[PAIRS * HID2];
__device__ float g_WKQ[PAIRS * HID];
__device__ float g_U[PAIRS * VD];
__device__ float g_R[PAIRS * VD];
__device__ float g_PH[PAIRS * HID];
__device__ float g_H[PAIRS * HID];
__device__ float g_Pacc[PAIRS * NCHUNK * VD];
__device__ float g_Pm[PAIRS * NCHUNK];
__device__ float g_Pl[PAIRS * NCHUNK];

// ---------------- init: bias-initialize split-K atomic outputs ----------------
__global__ void init_kernel(const float* __restrict__ bqp,
                            const float* __restrict__ bvp,
                            const float* __restrict__ b1) {
    int t = blockIdx.x * blockDim.x + threadIdx.x;
    if (t < PAIRS * HID2) {
        int col = t & (HID2 - 1);
        g_X[t]  = (col < HID) ? 0.f : bqp[col - HID];
        g_QQ[t] = 0.f;
    }
    if (t < PAIRS * HID) {
        int col = t & (HID - 1);
        g_WKQ[t] = 0.f;
        g_PH[t]  = bvp[col];
        g_H[t]   = b1[col];
    }
    if (t < PAIRS * VD) g_U[t] = 0.f;
}

// ---------------- skinny GEMM v3: single k-tile, max block count --------------
// (unchanged from R6 WIN config)
template <bool TN>
__global__ __launch_bounds__(128)
void gemm_t(const float* __restrict__ in, int in_ld,
            const float* __restrict__ W, int wld,
            float* __restrict__ out, int out_ld,
            float scale) {
    __shared__ float As[32][18];
    __shared__ float Bs[32][68];

    const int tx = threadIdx.x;
    const int r0 = blockIdx.x * 64;
    const int p0 = blockIdx.y * 16;
    const int k0 = blockIdx.z * 32;

    {
        const int p  = tx >> 3;
        const int kq = tx & 7;
        float4 v = *(const float4*)(in + (size_t)(p0 + p) * in_ld + k0 + 4 * kq);
        As[4 * kq + 0][p] = v.x;
        As[4 * kq + 1][p] = v.y;
        As[4 * kq + 2][p] = v.z;
        As[4 * kq + 3][p] = v.w;
    }
    if (TN) {
#pragma unroll
        for (int i = 0; i < 4; i++) {
            int idx = tx + 128 * i;
            int kk = idx >> 4, c = idx & 15;
            *(float4*)&Bs[kk][4 * c] =
                *(const float4*)(W + (size_t)(k0 + kk) * wld + r0 + 4 * c);
        }
    } else {
#pragma unroll
        for (int i = 0; i < 4; i++) {
            int idx = tx + 128 * i;
            int r = idx >> 3, kq = idx & 7;
            float4 v = *(const float4*)(W + (size_t)(r0 + r) * wld + k0 + 4 * kq);
            Bs[4 * kq + 0][r] = v.x;
            Bs[4 * kq + 1][r] = v.y;
            Bs[4 * kq + 2][r] = v.z;
            Bs[4 * kq + 3][r] = v.w;
        }
    }
    __syncthreads();

    const int w = tx >> 5;
    const int lane = tx & 31;
    const int tp = lane >> 2;
    const int rcol = 16 * w + 4 * (lane & 3);

    float acc[2][4] = {{0.f, 0.f, 0.f, 0.f}, {0.f, 0.f, 0.f, 0.f}};

#pragma unroll
    for (int kk = 0; kk < 32; kk++) {
        float2 a2 = *(const float2*)&As[kk][2 * tp];
        float4 b4 = *(const float4*)&Bs[kk][rcol];
        acc[0][0] += a2.x * b4.x; acc[0][1] += a2.x * b4.y;
        acc[0][2] += a2.x * b4.z; acc[0][3] += a2.x * b4.w;
        acc[1][0] += a2.y * b4.x; acc[1][1] += a2.y * b4.y;
        acc[1][2] += a2.y * b4.z; acc[1][3] += a2.y * b4.w;
    }

#pragma unroll
    for (int i = 0; i < 2; i++) {
        float* o = out + (size_t)(p0 + 2 * tp + i) * out_ld + r0 + rcol;
#pragma unroll
        for (int j = 0; j < 4; j++)
            atomicAdd(o + j, acc[i][j] * scale);
    }
}

// ---------------- flash v2: software-pipelined row loads ----------------------
// grid = (NCHUNK, PAIRS), 128 threads (4 warps). Warp w handles rows w, w+4, ...
// Rows double-buffered in registers (xa/xb): row j+1's 6 LDG.128 are in flight
// while row j's dot/shfl/exp/accumulate executes -> BW-bound, not latency-bound.
__global__ __launch_bounds__(128)
void flash_kernel(const float* __restrict__ video) {
    const int chunk = blockIdx.x;
    const int pair  = blockIdx.y;
    const int t = threadIdx.x;
    const int w = t >> 5, lane = t & 31;

    const float4* u4 = (const float4*)(g_U + (size_t)pair * VD);
    float4 uv[6];
#pragma unroll
    for (int j = 0; j < 6; j++) uv[j] = u4[lane + 32 * j];

    float m = -1e30f, l = 0.f;
    float4 acc[6];
#pragma unroll
    for (int j = 0; j < 6; j++) acc[j] = make_float4(0.f, 0.f, 0.f, 0.f);

    // rows for warp w: w + 4*j, j = 0..15 (ROWS_PER_CHUNK/FWARPS = 16, even)
    const float4* rbase = (const float4*)(video +
        ((size_t)pair * SEQ + (size_t)chunk * ROWS_PER_CHUNK + w) * VD) + lane;
    const size_t rstep = (size_t)FWARPS * (VD / 4);   // 4 rows in float4 units

    float4 xa[6], xb[6];

#define LOADROW(buf, j)  { const float4* p = rbase + (size_t)(j) * rstep; \
    buf[0]=p[0]; buf[1]=p[32]; buf[2]=p[64]; buf[3]=p[96]; buf[4]=p[128]; buf[5]=p[160]; }

#define PROCESS(buf) { \
    float s = 0.f; \
    _Pragma("unroll") \
    for (int jj = 0; jj < 6; jj++) \
        s += buf[jj].x * uv[jj].x + buf[jj].y * uv[jj].y \
           + buf[jj].z * uv[jj].z + buf[jj].w * uv[jj].w; \
    _Pragma("unroll") \
    for (int o = 16; o > 0; o >>= 1) s += __shfl_xor_sync(0xffffffffu, s, o); \
    if (s > m) { \
        float corr = __expf(m - s); \
        l *= corr; \
        _Pragma("unroll") \
        for (int jj = 0; jj < 6; jj++) { \
            acc[jj].x *= corr; acc[jj].y *= corr; \
            acc[jj].z *= corr; acc[jj].w *= corr; } \
        m = s; } \
    float p = __expf(s - m); \
    l += p; \
    _Pragma("unroll") \
    for (int jj = 0; jj < 6; jj++) { \
        acc[jj].x += p * buf[jj].x; acc[jj].y += p * buf[jj].y; \
        acc[jj].z += p * buf[jj].z; acc[jj].w += p * buf[jj].w; } }

    LOADROW(xa, 0)
#pragma unroll 1
    for (int j = 0; j < 16; j += 2) {
        LOADROW(xb, j + 1)
        PROCESS(xa)
        if (j + 2 < 16) LOADROW(xa, j + 2)
        PROCESS(xb)
    }
#undef LOADROW
#undef PROCESS

    __shared__ float sm[FWARPS], sl[FWARPS];
    __shared__ float sacc[FWARPS][VD];
    if (lane == 0) { sm[w] = m; sl[w] = l; }
    float4* sa4 = (float4*)sacc[w];
#pragma unroll
    for (int j = 0; j < 6; j++) sa4[lane + 32 * j] = acc[j];
    __syncthreads();

    float M = sm[0];
#pragma unroll
    for (int i = 1; i < FWARPS; i++) M = fmaxf(M, sm[i]);
    float wsc[FWARPS], L = 0.f;
#pragma unroll
    for (int i = 0; i < FWARPS; i++) { wsc[i] = __expf(sm[i] - M); L += wsc[i] * sl[i]; }

    for (int d = t; d < VD; d += 128) {
        float a = 0.f;
#pragma unroll
        for (int i = 0; i < FWARPS; i++) a += wsc[i] * sacc[i][d];
        g_Pacc[((size_t)pair * NCHUNK + chunk) * VD + d] = a;
    }
    if (t == 0) { g_Pm[pair * NCHUNK + chunk] = M; g_Pl[pair * NCHUNK + chunk] = L; }
}

// ---------------- combine split-S partials -> r = attn^T @ video ----------------
__global__ __launch_bounds__(256)
void combine_kernel() {
    const int pair = blockIdx.x, t = threadIdx.x;
    __shared__ float wsc[NCHUNK];
    __shared__ float sInvL;
    if (t == 0) {
        float M = g_Pm[pair * NCHUNK];
        for (int c = 1; c < NCHUNK; c++) M = fmaxf(M, g_Pm[pair * NCHUNK + c]);
        float L = 0.f;
        for (int c = 0; c < NCHUNK; c++) {
            float e = __expf(g_Pm[pair * NCHUNK + c] - M);
            wsc[c] = e;
            L += e * g_Pl[pair * NCHUNK + c];
        }
        sInvL = 1.f / L;
    }
    __syncthreads();
    const float invL = sInvL;
    for (int d = t; d < VD; d += 256) {
        float a = 0.f;
#pragma unroll
        for (int c = 0; c < NCHUNK; c++)
            a += wsc[c] * g_Pacc[((size_t)pair * NCHUNK + c) * VD + d];
        g_R[(size_t)pair * VD + d] = a * invL;
    }
}

// ---------------- final: out = softmax(relu(h) @ W2^T + b2 + mask) ----------------
__global__ __launch_bounds__(32)
void final_kernel(const float* __restrict__ W2, const float* __restrict__ b2,
                  const float* __restrict__ omask, float* __restrict__ out) {
    const int pair = blockIdx.x, lane = threadIdx.x;
    float o[NOUT] = {0.f, 0.f, 0.f, 0.f, 0.f};
    for (int h = lane; h < HID; h += 32) {
        float hv = fmaxf(g_H[pair * HID + h], 0.f);
#pragma unroll
        for (int j = 0; j < NOUT; j++) o[j] += hv * W2[j * HID + h];
    }
#pragma unroll
    for (int j = 0; j < NOUT; j++)
#pragma unroll
        for (int off = 16; off > 0; off >>= 1)
            o[j] += __shfl_xor_sync(0xffffffffu, o[j], off);
    if (lane == 0) {
        float x[NOUT], mx = -1e30f;
#pragma unroll
        for (int j = 0; j < NOUT; j++) {
            x[j] = o[j] + b2[j] + omask[pair * NOUT + j];
            mx = fmaxf(mx, x[j]);
        }
        float e[NOUT], s = 0.f;
#pragma unroll
        for (int j = 0; j < NOUT; j++) { e[j] = __expf(x[j] - mx); s += e[j]; }
#pragma unroll
        for (int j = 0; j < NOUT; j++) out[pair * NOUT + j] = e[j] / s;
    }
}

// ---------------- launch ----------------
extern "C" void kernel_launch(void* const* d_in, const int* in_sizes, int n_in,
                              void* d_out, int out_size) {
    (void)in_sizes; (void)n_in; (void)out_size;
    const float* video = (const float*)d_in[0];
    const float* ques  = (const float*)d_in[1];
    const float* omask = (const float*)d_in[3];
    const float* Wvp   = (const float*)d_in[4];
    const float* bvp   = (const float*)d_in[5];
    const float* Wqp   = (const float*)d_in[6];
    const float* bqp   = (const float*)d_in[7];
    const float* Wk    = (const float*)d_in[8];
    const float* Wv    = (const float*)d_in[9];
    const float* Wq    = (const float*)d_in[10];
    const float* W1    = (const float*)d_in[11];
    const float* b1    = (const float*)d_in[12];
    const float* W2    = (const float*)d_in[13];
    const float* b2    = (const float*)d_in[14];
    float* out = (float*)d_out;

    float *X, *QQ, *WKQ, *U, *R, *PH, *H;
    cudaGetSymbolAddress((void**)&X,   g_X);
    cudaGetSymbolAddress((void**)&QQ,  g_QQ);
    cudaGetSymbolAddress((void**)&WKQ, g_WKQ);
    cudaGetSymbolAddress((void**)&U,   g_U);
    cudaGetSymbolAddress((void**)&R,   g_R);
    cudaGetSymbolAddress((void**)&PH,  g_PH);
    cudaGetSymbolAddress((void**)&H,   g_H);

    dim3 blk(128);

    // biases into atomic-accumulated outputs
    init_kernel<<<(PAIRS * HID2 + 255) / 256, 256>>>(bqp, bvp, b1);
    // q = ques[:,:,0,:] @ Wqp^T + bqp -> X[:,512:]   (K=768, R=512, NT)
    gemm_t<false><<<dim3(8, 5, 24), blk>>>(ques, 32 * VD, Wqp, VD, X + HID, HID2, 1.f);
    // qq = q @ Wq^T                                   (K=512, R=1024, NT)
    gemm_t<false><<<dim3(16, 5, 16), blk>>>(X + HID, HID2, Wq, HID, QQ, HID2, 1.f);
    // wkq = Wk^T @ qq                                 (K=1024, R=512, TN)
    gemm_t<true ><<<dim3(8, 5, 32), blk>>>(QQ, HID2, Wk, HID, WKQ, HID, 1.f);
    // u = Wvp^T @ wkq / sqrt(2H)                      (K=512, R=768, TN)
    gemm_t<true ><<<dim3(12, 5, 16), blk>>>(WKQ, HID, Wvp, VD, U, VD, 1.f / 32.f);
    // flash: single HBM pass over video_enc (pipelined row loads)
    flash_kernel<<<dim3(NCHUNK, PAIRS), 128>>>(video);
    combine_kernel<<<PAIRS, 256>>>();
    // pooled_h = r @ Wvp^T + bvp                       (K=768, R=512, NT)
    gemm_t<false><<<dim3(8, 5, 24), blk>>>(R, VD, Wvp, VD, PH, HID, 1.f);
    // pooled_v = pooled_h @ Wv^T -> X[:, :512]         (K=512, R=512, NT)
    gemm_t<false><<<dim3(8, 5, 16), blk>>>(PH, HID, Wv, HID, X, HID2, 1.f);
    // h = X @ W1^T + b1 (relu deferred)                (K=1024, R=512, NT)
    gemm_t<false><<<dim3(8, 5, 32), blk>>>(X, HID2, W1, HID2, H, HID, 1.f);
    // out = softmax(relu(h) @ W2^T + b2 + output_mask)
    final_kernel<<<PAIRS, 32>>>(W2, b2, omask, out);
}

// round 8
// speedup vs baseline: 1.0363x; 1.0363x over previous
#include <cuda_runtime.h>

#define PAIRS 80
#define SEQ   2048
#define VD    768
#define HID   512
#define HID2  1024
#define NOUT  5
#define NCHUNK 16
#define ROWS_PER_CHUNK (SEQ / NCHUNK)   // 128

// ---------------- scratch (static device globals; no allocs) ----------------
__device__ float g_X[PAIRS * HID2];     // concat: [:,0:512]=pooled_v, [:,512:1024]=q
__device__ float g_QQ[PAIRS * HID2];
__device__ float g_WKQ[PAIRS * HID];
__device__ float g_U[PAIRS * VD];
__device__ float g_R[PAIRS * VD];
__device__ float g_PH[PAIRS * HID];
__device__ float g_H[PAIRS * HID];
__device__ float g_Pacc[PAIRS * NCHUNK * VD];
__device__ float g_Pm[PAIRS * NCHUNK];
__device__ float g_Pl[PAIRS * NCHUNK];

// ---------------- init: bias-initialize split-K atomic outputs ----------------
__global__ void init_kernel(const float* __restrict__ bqp,
                            const float* __restrict__ bvp,
                            const float* __restrict__ b1) {
    int t = blockIdx.x * blockDim.x + threadIdx.x;
    if (t < PAIRS * HID2) {
        int col = t & (HID2 - 1);
        g_X[t]  = (col < HID) ? 0.f : bqp[col - HID];
        g_QQ[t] = 0.f;
    }
    if (t < PAIRS * HID) {
        int col = t & (HID - 1);
        g_WKQ[t] = 0.f;
        g_PH[t]  = bvp[col];
        g_H[t]   = b1[col];
    }
    if (t < PAIRS * VD) g_U[t] = 0.f;
}

// ---------------- skinny GEMM v4: R6 tile + small k-loop ----------------------
// out[p][r] += scale * sum_k in[p][k] * W(k,r)
// Block: 128 threads, tile 16 pairs x 64 r, k-step 32, niter tiles per block
// (kchunk = 32*niter), double-buffered smem + register prefetch.
// z = K/(32*niter) = 8 everywhere: grids 320-640 blocks (~2/SM, 1 wave),
// atomic lanes / niter vs R6 (epilogue was the hidden 4-5us term).
// TN: W is [K, R]. NT: W is [R, K] row-major.
template <bool TN>
__global__ __launch_bounds__(128)
void gemm_t2(const float* __restrict__ in, int in_ld,
             const float* __restrict__ W, int wld,
             float* __restrict__ out, int out_ld,
             int niter, float scale) {
    __shared__ float As[2][32][18];   // [kk][pair] transposed
    __shared__ float Bs[2][32][68];   // [kk][r]

    const int tx = threadIdx.x;
    const int r0 = blockIdx.x * 64;
    const int p0 = blockIdx.y * 16;
    const int kbase = blockIdx.z * 32 * niter;

    const int apk = tx >> 3;    // pair for A load
    const int akq = tx & 7;     // f4 k-group for A load

    float4 apf;
    float4 bpf[4];

    auto ldtile = [&](int k0) {
        apf = *(const float4*)(in + (size_t)(p0 + apk) * in_ld + k0 + 4 * akq);
        if (TN) {
#pragma unroll
            for (int i = 0; i < 4; i++) {
                int idx = tx + 128 * i;
                int kk = idx >> 4, c = idx & 15;
                bpf[i] = *(const float4*)(W + (size_t)(k0 + kk) * wld + r0 + 4 * c);
            }
        } else {
#pragma unroll
            for (int i = 0; i < 4; i++) {
                int idx = tx + 128 * i;
                int r = idx >> 3, kq = idx & 7;
                bpf[i] = *(const float4*)(W + (size_t)(r0 + r) * wld + k0 + 4 * kq);
            }
        }
    };
    auto sttile = [&](int buf) {
        As[buf][4 * akq + 0][apk] = apf.x;
        As[buf][4 * akq + 1][apk] = apf.y;
        As[buf][4 * akq + 2][apk] = apf.z;
        As[buf][4 * akq + 3][apk] = apf.w;
        if (TN) {
#pragma unroll
            for (int i = 0; i < 4; i++) {
                int idx = tx + 128 * i;
                int kk = idx >> 4, c = idx & 15;
                *(float4*)&Bs[buf][kk][4 * c] = bpf[i];
            }
        } else {
#pragma unroll
            for (int i = 0; i < 4; i++) {
                int idx = tx + 128 * i;
                int r = idx >> 3, kq = idx & 7;
                Bs[buf][4 * kq + 0][r] = bpf[i].x;
                Bs[buf][4 * kq + 1][r] = bpf[i].y;
                Bs[buf][4 * kq + 2][r] = bpf[i].z;
                Bs[buf][4 * kq + 3][r] = bpf[i].w;
            }
        }
    };

    ldtile(kbase);
    sttile(0);
    __syncthreads();

    const int w = tx >> 5;
    const int lane = tx & 31;
    const int tp = lane >> 2;                 // 2-pair group
    const int rcol = 16 * w + 4 * (lane & 3); // 4-r group

    float acc[2][4] = {{0.f, 0.f, 0.f, 0.f}, {0.f, 0.f, 0.f, 0.f}};

    for (int it = 0; it < niter; it++) {
        const int cur = it & 1;
        const bool more = (it + 1 < niter);
        if (more) ldtile(kbase + 32 * (it + 1));   // overlaps compute below
#pragma unroll
        for (int kk = 0; kk < 32; kk++) {
            float2 a2 = *(const float2*)&As[cur][kk][2 * tp];
            float4 b4 = *(const float4*)&Bs[cur][kk][rcol];
            acc[0][0] += a2.x * b4.x; acc[0][1] += a2.x * b4.y;
            acc[0][2] += a2.x * b4.z; acc[0][3] += a2.x * b4.w;
            acc[1][0] += a2.y * b4.x; acc[1][1] += a2.y * b4.y;
            acc[1][2] += a2.y * b4.z; acc[1][3] += a2.y * b4.w;
        }
        if (more) {
            sttile(cur ^ 1);
            __syncthreads();
        }
    }

#pragma unroll
    for (int i = 0; i < 2; i++) {
        float* o = out + (size_t)(p0 + 2 * tp + i) * out_ld + r0 + rcol;
#pragma unroll
        for (int j = 0; j < 4; j++)
            atomicAdd(o + j, acc[i][j] * scale);
    }
}

// ---------------- flash (R6 WIN version): single row buffer, no spills --------
// grid = (NCHUNK, PAIRS), 256 threads (8 warps). Warp handles rows w, w+8, ...
__global__ __launch_bounds__(256)
void flash_kernel(const float* __restrict__ video) {
    const int chunk = blockIdx.x;
    const int pair  = blockIdx.y;
    const int t = threadIdx.x;
    const int w = t >> 5, lane = t & 31;

    const float4* u4 = (const float4*)(g_U + (size_t)pair * VD);
    float4 uv[6];
#pragma unroll
    for (int j = 0; j < 6; j++) uv[j] = u4[lane + 32 * j];

    float m = -1e30f, l = 0.f;
    float4 acc[6];
#pragma unroll
    for (int j = 0; j < 6; j++) acc[j] = make_float4(0.f, 0.f, 0.f, 0.f);

    const float* base = video + ((size_t)pair * SEQ + (size_t)chunk * ROWS_PER_CHUNK) * VD;

    for (int r = w; r < ROWS_PER_CHUNK; r += 8) {
        const float4* x4 = (const float4*)(base + (size_t)r * VD);
        float4 xv[6];
#pragma unroll
        for (int j = 0; j < 6; j++) xv[j] = x4[lane + 32 * j];
        float s = 0.f;
#pragma unroll
        for (int j = 0; j < 6; j++)
            s += xv[j].x * uv[j].x + xv[j].y * uv[j].y + xv[j].z * uv[j].z + xv[j].w * uv[j].w;
#pragma unroll
        for (int o = 16; o > 0; o >>= 1) s += __shfl_xor_sync(0xffffffffu, s, o);

        if (s > m) {                     // warp-uniform; rare after warmup
            float corr = __expf(m - s);
            l *= corr;
#pragma unroll
            for (int j = 0; j < 6; j++) {
                acc[j].x *= corr; acc[j].y *= corr;
                acc[j].z *= corr; acc[j].w *= corr;
            }
            m = s;
        }
        float p = __expf(s - m);
        l += p;
#pragma unroll
        for (int j = 0; j < 6; j++) {
            acc[j].x += p * xv[j].x; acc[j].y += p * xv[j].y;
            acc[j].z += p * xv[j].z; acc[j].w += p * xv[j].w;
        }
    }

    __shared__ float sm[8], sl[8];
    __shared__ float sacc[8][VD];
    if (lane == 0) { sm[w] = m; sl[w] = l; }
    float4* sa4 = (float4*)sacc[w];
#pragma unroll
    for (int j = 0; j < 6; j++) sa4[lane + 32 * j] = acc[j];
    __syncthreads();

    float M = sm[0];
#pragma unroll
    for (int i = 1; i < 8; i++) M = fmaxf(M, sm[i]);
    float wsc[8], L = 0.f;
#pragma unroll
    for (int i = 0; i < 8; i++) { wsc[i] = __expf(sm[i] - M); L += wsc[i] * sl[i]; }

    for (int d = t; d < VD; d += 256) {
        float a = 0.f;
#pragma unroll
        for (int i = 0; i < 8; i++) a += wsc[i] * sacc[i][d];
        g_Pacc[((size_t)pair * NCHUNK + chunk) * VD + d] = a;
    }
    if (t == 0) { g_Pm[pair * NCHUNK + chunk] = M; g_Pl[pair * NCHUNK + chunk] = L; }
}

// ---------------- combine split-S partials -> r = attn^T @ video ----------------
__global__ __launch_bounds__(256)
void combine_kernel() {
    const int pair = blockIdx.x, t = threadIdx.x;
    __shared__ float wsc[NCHUNK];
    __shared__ float sInvL;
    if (t == 0) {
        float M = g_Pm[pair * NCHUNK];
        for (int c = 1; c < NCHUNK; c++) M = fmaxf(M, g_Pm[pair * NCHUNK + c]);
        float L = 0.f;
        for (int c = 0; c < NCHUNK; c++) {
            float e = __expf(g_Pm[pair * NCHUNK + c] - M);
            wsc[c] = e;
            L += e * g_Pl[pair * NCHUNK + c];
        }
        sInvL = 1.f / L;
    }
    __syncthreads();
    const float invL = sInvL;
    for (int d = t; d < VD; d += 256) {
        float a = 0.f;
#pragma unroll
        for (int c = 0; c < NCHUNK; c++)
            a += wsc[c] * g_Pacc[((size_t)pair * NCHUNK + c) * VD + d];
        g_R[(size_t)pair * VD + d] = a * invL;
    }
}

// ---------------- final: out = softmax(relu(h) @ W2^T + b2 + mask) ----------------
__global__ __launch_bounds__(32)
void final_kernel(const float* __restrict__ W2, const float* __restrict__ b2,
                  const float* __restrict__ omask, float* __restrict__ out) {
    const int pair = blockIdx.x, lane = threadIdx.x;
    float o[NOUT] = {0.f, 0.f, 0.f, 0.f, 0.f};
    for (int h = lane; h < HID; h += 32) {
        float hv = fmaxf(g_H[pair * HID + h], 0.f);
#pragma unroll
        for (int j = 0; j < NOUT; j++) o[j] += hv * W2[j * HID + h];
    }
#pragma unroll
    for (int j = 0; j < NOUT; j++)
#pragma unroll
        for (int off = 16; off > 0; off >>= 1)
            o[j] += __shfl_xor_sync(0xffffffffu, o[j], off);
    if (lane == 0) {
        float x[NOUT], mx = -1e30f;
#pragma unroll
        for (int j = 0; j < NOUT; j++) {
            x[j] = o[j] + b2[j] + omask[pair * NOUT + j];
            mx = fmaxf(mx, x[j]);
        }
        float e[NOUT], s = 0.f;
#pragma unroll
        for (int j = 0; j < NOUT; j++) { e[j] = __expf(x[j] - mx); s += e[j]; }
#pragma unroll
        for (int j = 0; j < NOUT; j++) out[pair * NOUT + j] = e[j] / s;
    }
}

// ---------------- launch ----------------
extern "C" void kernel_launch(void* const* d_in, const int* in_sizes, int n_in,
                              void* d_out, int out_size) {
    (void)in_sizes; (void)n_in; (void)out_size;
    const float* video = (const float*)d_in[0];
    const float* ques  = (const float*)d_in[1];
    const float* omask = (const float*)d_in[3];
    const float* Wvp   = (const float*)d_in[4];
    const float* bvp   = (const float*)d_in[5];
    const float* Wqp   = (const float*)d_in[6];
    const float* bqp   = (const float*)d_in[7];
    const float* Wk    = (const float*)d_in[8];
    const float* Wv    = (const float*)d_in[9];
    const float* Wq    = (const float*)d_in[10];
    const float* W1    = (const float*)d_in[11];
    const float* b1    = (const float*)d_in[12];
    const float* W2    = (const float*)d_in[13];
    const float* b2    = (const float*)d_in[14];
    float* out = (float*)d_out;

    float *X, *QQ, *WKQ, *U, *R, *PH, *H;
    cudaGetSymbolAddress((void**)&X,   g_X);
    cudaGetSymbolAddress((void**)&QQ,  g_QQ);
    cudaGetSymbolAddress((void**)&WKQ, g_WKQ);
    cudaGetSymbolAddress((void**)&U,   g_U);
    cudaGetSymbolAddress((void**)&R,   g_R);
    cudaGetSymbolAddress((void**)&PH,  g_PH);
    cudaGetSymbolAddress((void**)&H,   g_H);

    dim3 blk(128);

    // biases into atomic-accumulated outputs
    init_kernel<<<(PAIRS * HID2 + 255) / 256, 256>>>(bqp, bvp, b1);
    // q = ques[:,:,0,:] @ Wqp^T + bqp -> X[:,512:]   (K=768, R=512, NT, niter=3)
    gemm_t2<false><<<dim3(8, 5, 8), blk>>>(ques, 32 * VD, Wqp, VD, X + HID, HID2, 3, 1.f);
    // qq = q @ Wq^T                                   (K=512, R=1024, NT, niter=2)
    gemm_t2<false><<<dim3(16, 5, 8), blk>>>(X + HID, HID2, Wq, HID, QQ, HID2, 2, 1.f);
    // wkq = Wk^T @ qq                                 (K=1024, R=512, TN, niter=4)
    gemm_t2<true ><<<dim3(8, 5, 8), blk>>>(QQ, HID2, Wk, HID, WKQ, HID, 4, 1.f);
    // u = Wvp^T @ wkq / sqrt(2H)                      (K=512, R=768, TN, niter=2)
    gemm_t2<true ><<<dim3(12, 5, 8), blk>>>(WKQ, HID, Wvp, VD, U, VD, 2, 1.f / 32.f);
    // flash: single HBM pass over video_enc
    flash_kernel<<<dim3(NCHUNK, PAIRS), 256>>>(video);
    combine_kernel<<<PAIRS, 256>>>();
    // pooled_h = r @ Wvp^T + bvp                       (K=768, R=512, NT, niter=3)
    gemm_t2<false><<<dim3(8, 5, 8), blk>>>(R, VD, Wvp, VD, PH, HID, 3, 1.f);
    // pooled_v = pooled_h @ Wv^T -> X[:, :512]         (K=512, R=512, NT, niter=2)
    gemm_t2<false><<<dim3(8, 5, 8), blk>>>(PH, HID, Wv, HID, X, HID2, 2, 1.f);
    // h = X @ W1^T + b1 (relu deferred)                (K=1024, R=512, NT, niter=4)
    gemm_t2<false><<<dim3(8, 5, 8), blk>>>(X, HID2, W1, HID2, H, HID, 4, 1.f);
    // out = softmax(relu(h) @ W2^T + b2 + output_mask)
    final_kernel<<<PAIRS, 32>>>(W2, b2, omask, out);
}

// round 9
// speedup vs baseline: 1.0661x; 1.0288x over previous
#include <cuda_runtime.h>
#include <cstdint>

#define PAIRS 80
#define SEQ   2048
#define VD    768
#define HID   512
#define HID2  1024
#define NOUT  5
#define NCHUNK 16
#define ROWS_PER_CHUNK (SEQ / NCHUNK)   // 128
#define G 8                              // rows per staging group
#define NG (ROWS_PER_CHUNK / G)          // 16 groups

// ---------------- scratch (static device globals; no allocs) ----------------
__device__ float g_X[PAIRS * HID2];     // concat: [:,0:512]=pooled_v, [:,512:1024]=q
__device__ float g_QQ[PAIRS * HID2];
__device__ float g_WKQ[PAIRS * HID];
__device__ float g_U[PAIRS * VD];
__device__ float g_R[PAIRS * VD];
__device__ float g_PH[PAIRS * HID];
__device__ float g_H[PAIRS * HID];
__device__ float g_Pacc[PAIRS * NCHUNK * VD];
__device__ float g_Pm[PAIRS * NCHUNK];
__device__ float g_Pl[PAIRS * NCHUNK];

// ---------------- init: bias-initialize split-K atomic outputs ----------------
__global__ void init_kernel(const float* __restrict__ bqp,
                            const float* __restrict__ bvp,
                            const float* __restrict__ b1) {
    int t = blockIdx.x * blockDim.x + threadIdx.x;
    if (t < PAIRS * HID2) {
        int col = t & (HID2 - 1);
        g_X[t]  = (col < HID) ? 0.f : bqp[col - HID];
        g_QQ[t] = 0.f;
    }
    if (t < PAIRS * HID) {
        int col = t & (HID - 1);
        g_WKQ[t] = 0.f;
        g_PH[t]  = bvp[col];
        g_H[t]   = b1[col];
    }
    if (t < PAIRS * VD) g_U[t] = 0.f;
}

// ---------------- skinny GEMM v4 (R8 WIN config, unchanged) -------------------
template <bool TN>
__global__ __launch_bounds__(128)
void gemm_t2(const float* __restrict__ in, int in_ld,
             const float* __restrict__ W, int wld,
             float* __restrict__ out, int out_ld,
             int niter, float scale) {
    __shared__ float As[2][32][18];   // [kk][pair] transposed
    __shared__ float Bs[2][32][68];   // [kk][r]

    const int tx = threadIdx.x;
    const int r0 = blockIdx.x * 64;
    const int p0 = blockIdx.y * 16;
    const int kbase = blockIdx.z * 32 * niter;

    const int apk = tx >> 3;
    const int akq = tx & 7;

    float4 apf;
    float4 bpf[4];

    auto ldtile = [&](int k0) {
        apf = *(const float4*)(in + (size_t)(p0 + apk) * in_ld + k0 + 4 * akq);
        if (TN) {
#pragma unroll
            for (int i = 0; i < 4; i++) {
                int idx = tx + 128 * i;
                int kk = idx >> 4, c = idx & 15;
                bpf[i] = *(const float4*)(W + (size_t)(k0 + kk) * wld + r0 + 4 * c);
            }
        } else {
#pragma unroll
            for (int i = 0; i < 4; i++) {
                int idx = tx + 128 * i;
                int r = idx >> 3, kq = idx & 7;
                bpf[i] = *(const float4*)(W + (size_t)(r0 + r) * wld + k0 + 4 * kq);
            }
        }
    };
    auto sttile = [&](int buf) {
        As[buf][4 * akq + 0][apk] = apf.x;
        As[buf][4 * akq + 1][apk] = apf.y;
        As[buf][4 * akq + 2][apk] = apf.z;
        As[buf][4 * akq + 3][apk] = apf.w;
        if (TN) {
#pragma unroll
            for (int i = 0; i < 4; i++) {
                int idx = tx + 128 * i;
                int kk = idx >> 4, c = idx & 15;
                *(float4*)&Bs[buf][kk][4 * c] = bpf[i];
            }
        } else {
#pragma unroll
            for (int i = 0; i < 4; i++) {
                int idx = tx + 128 * i;
                int r = idx >> 3, kq = idx & 7;
                Bs[buf][4 * kq + 0][r] = bpf[i].x;
                Bs[buf][4 * kq + 1][r] = bpf[i].y;
                Bs[buf][4 * kq + 2][r] = bpf[i].z;
                Bs[buf][4 * kq + 3][r] = bpf[i].w;
            }
        }
    };

    ldtile(kbase);
    sttile(0);
    __syncthreads();

    const int w = tx >> 5;
    const int lane = tx & 31;
    const int tp = lane >> 2;
    const int rcol = 16 * w + 4 * (lane & 3);

    float acc[2][4] = {{0.f, 0.f, 0.f, 0.f}, {0.f, 0.f, 0.f, 0.f}};

    for (int it = 0; it < niter; it++) {
        const int cur = it & 1;
        const bool more = (it + 1 < niter);
        if (more) ldtile(kbase + 32 * (it + 1));
#pragma unroll
        for (int kk = 0; kk < 32; kk++) {
            float2 a2 = *(const float2*)&As[cur][kk][2 * tp];
            float4 b4 = *(const float4*)&Bs[cur][kk][rcol];
            acc[0][0] += a2.x * b4.x; acc[0][1] += a2.x * b4.y;
            acc[0][2] += a2.x * b4.z; acc[0][3] += a2.x * b4.w;
            acc[1][0] += a2.y * b4.x; acc[1][1] += a2.y * b4.y;
            acc[1][2] += a2.y * b4.z; acc[1][3] += a2.y * b4.w;
        }
        if (more) {
            sttile(cur ^ 1);
            __syncthreads();
        }
    }

#pragma unroll
    for (int i = 0; i < 2; i++) {
        float* o = out + (size_t)(p0 + 2 * tp + i) * out_ld + r0 + rcol;
#pragma unroll
        for (int j = 0; j < 4; j++)
            atomicAdd(o + j, acc[i][j] * scale);
    }
}

// ---------------- flash v3: cp.async smem-staged row pipeline -----------------
// grid = (NCHUNK, PAIRS), 256 threads (8 warps). Rows staged in groups of G=8
// (24KB) into a double-buffered smem ring via cp.async.cg (no register cost for
// in-flight data): group g+1's LDGSTS are outstanding while group g computes
// -> staging-BW-bound. Warp w computes row w of each group (global rows w, w+8..).
__global__ __launch_bounds__(256)
void flash_kernel(const float* __restrict__ video) {
    extern __shared__ float smem[];          // [2][G][VD] ring = 48KB
    const int chunk = blockIdx.x;
    const int pair  = blockIdx.y;
    const int t = threadIdx.x;
    const int w = t >> 5, lane = t & 31;

    const float4* u4 = (const float4*)(g_U + (size_t)pair * VD);
    float4 uv[6];
#pragma unroll
    for (int j = 0; j < 6; j++) uv[j] = u4[lane + 32 * j];

    const float* base = video + ((size_t)pair * SEQ + (size_t)chunk * ROWS_PER_CHUNK) * VD;

    // stage group g into ring buffer b: G rows x 192 f4 = 1536 LDGSTS over 256 thr
    auto stage = [&](int b, int g) {
        const float* src = base + (size_t)g * G * VD;
        float* dst = smem + (size_t)b * (G * VD);
#pragma unroll
        for (int i = 0; i < 6; i++) {
            int idx = t + 256 * i;               // 0..1535
            int row = idx / 192, c4 = idx % 192;
            uint32_t sa = (uint32_t)__cvta_generic_to_shared(dst + (size_t)row * VD + 4 * c4);
            asm volatile("cp.async.cg.shared.global [%0], [%1], 16;\n"
                         :: "r"(sa), "l"(src + (size_t)row * VD + 4 * c4));
        }
        asm volatile("cp.async.commit_group;\n");
    };

    float m = -1e30f, l = 0.f;
    float4 acc[6];
#pragma unroll
    for (int j = 0; j < 6; j++) acc[j] = make_float4(0.f, 0.f, 0.f, 0.f);

    stage(0, 0);
#pragma unroll 1
    for (int g = 0; g < NG; g++) {
        if (g + 1 < NG) {
            stage((g + 1) & 1, g + 1);
            asm volatile("cp.async.wait_group 1;\n");
        } else {
            asm volatile("cp.async.wait_group 0;\n");
        }
        __syncthreads();

        const float4* x4 = (const float4*)(smem + (size_t)(g & 1) * (G * VD) + (size_t)w * VD);
        float4 xv[6];
#pragma unroll
        for (int j = 0; j < 6; j++) xv[j] = x4[lane + 32 * j];
        float s = 0.f;
#pragma unroll
        for (int j = 0; j < 6; j++)
            s += xv[j].x * uv[j].x + xv[j].y * uv[j].y + xv[j].z * uv[j].z + xv[j].w * uv[j].w;
#pragma unroll
        for (int o = 16; o > 0; o >>= 1) s += __shfl_xor_sync(0xffffffffu, s, o);

        if (s > m) {                     // warp-uniform; rare after warmup
            float corr = __expf(m - s);
            l *= corr;
#pragma unroll
            for (int j = 0; j < 6; j++) {
                acc[j].x *= corr; acc[j].y *= corr;
                acc[j].z *= corr; acc[j].w *= corr;
            }
            m = s;
        }
        float p = __expf(s - m);
        l += p;
#pragma unroll
        for (int j = 0; j < 6; j++) {
            acc[j].x += p * xv[j].x; acc[j].y += p * xv[j].y;
            acc[j].z += p * xv[j].z; acc[j].w += p * xv[j].w;
        }
        __syncthreads();                 // buffer (g&1) free for reuse at g+2
    }

    // ---- cross-warp combine; sacc overlays the (now idle) ring buffer ----
    __shared__ float sm[8], sl[8];
    if (lane == 0) { sm[w] = m; sl[w] = l; }
    float* sacc = smem;                  // 8 x VD floats (24KB of the 48KB ring)
    float4* sa4 = (float4*)(sacc + (size_t)w * VD);
#pragma unroll
    for (int j = 0; j < 6; j++) sa4[lane + 32 * j] = acc[j];
    __syncthreads();

    float M = sm[0];
#pragma unroll
    for (int i = 1; i < 8; i++) M = fmaxf(M, sm[i]);
    float wsc[8], L = 0.f;
#pragma unroll
    for (int i = 0; i < 8; i++) { wsc[i] = __expf(sm[i] - M); L += wsc[i] * sl[i]; }

    for (int d = t; d < VD; d += 256) {
        float a = 0.f;
#pragma unroll
        for (int i = 0; i < 8; i++) a += wsc[i] * sacc[(size_t)i * VD + d];
        g_Pacc[((size_t)pair * NCHUNK + chunk) * VD + d] = a;
    }
    if (t == 0) { g_Pm[pair * NCHUNK + chunk] = M; g_Pl[pair * NCHUNK + chunk] = L; }
}

// ---------------- combine split-S partials -> r = attn^T @ video ----------------
__global__ __launch_bounds__(256)
void combine_kernel() {
    const int pair = blockIdx.x, t = threadIdx.x;
    __shared__ float wsc[NCHUNK];
    __shared__ float sInvL;
    if (t == 0) {
        float M = g_Pm[pair * NCHUNK];
        for (int c = 1; c < NCHUNK; c++) M = fmaxf(M, g_Pm[pair * NCHUNK + c]);
        float L = 0.f;
        for (int c = 0; c < NCHUNK; c++) {
            float e = __expf(g_Pm[pair * NCHUNK + c] - M);
            wsc[c] = e;
            L += e * g_Pl[pair * NCHUNK + c];
        }
        sInvL = 1.f / L;
    }
    __syncthreads();
    const float invL = sInvL;
    for (int d = t; d < VD; d += 256) {
        float a = 0.f;
#pragma unroll
        for (int c = 0; c < NCHUNK; c++)
            a += wsc[c] * g_Pacc[((size_t)pair * NCHUNK + c) * VD + d];
        g_R[(size_t)pair * VD + d] = a * invL;
    }
}

// ---------------- final: out = softmax(relu(h) @ W2^T + b2 + mask) ----------------
__global__ __launch_bounds__(32)
void final_kernel(const float* __restrict__ W2, const float* __restrict__ b2,
                  const float* __restrict__ omask, float* __restrict__ out) {
    const int pair = blockIdx.x, lane = threadIdx.x;
    float o[NOUT] = {0.f, 0.f, 0.f, 0.f, 0.f};
    for (int h = lane; h < HID; h += 32) {
        float hv = fmaxf(g_H[pair * HID + h], 0.f);
#pragma unroll
        for (int j = 0; j < NOUT; j++) o[j] += hv * W2[j * HID + h];
    }
#pragma unroll
    for (int j = 0; j < NOUT; j++)
#pragma unroll
        for (int off = 16; off > 0; off >>= 1)
            o[j] += __shfl_xor_sync(0xffffffffu, o[j], off);
    if (lane == 0) {
        float x[NOUT], mx = -1e30f;
#pragma unroll
        for (int j = 0; j < NOUT; j++) {
            x[j] = o[j] + b2[j] + omask[pair * NOUT + j];
            mx = fmaxf(mx, x[j]);
        }
        float e[NOUT], s = 0.f;
#pragma unroll
        for (int j = 0; j < NOUT; j++) { e[j] = __expf(x[j] - mx); s += e[j]; }
#pragma unroll
        for (int j = 0; j < NOUT; j++) out[pair * NOUT + j] = e[j] / s;
    }
}

// ---------------- launch ----------------
extern "C" void kernel_launch(void* const* d_in, const int* in_sizes, int n_in,
                              void* d_out, int out_size) {
    (void)in_sizes; (void)n_in; (void)out_size;
    const float* video = (const float*)d_in[0];
    const float* ques  = (const float*)d_in[1];
    const float* omask = (const float*)d_in[3];
    const float* Wvp   = (const float*)d_in[4];
    const float* bvp   = (const float*)d_in[5];
    const float* Wqp   = (const float*)d_in[6];
    const float* bqp   = (const float*)d_in[7];
    const float* Wk    = (const float*)d_in[8];
    const float* Wv    = (const float*)d_in[9];
    const float* Wq    = (const float*)d_in[10];
    const float* W1    = (const float*)d_in[11];
    const float* b1    = (const float*)d_in[12];
    const float* W2    = (const float*)d_in[13];
    const float* b2    = (const float*)d_in[14];
    float* out = (float*)d_out;

    float *X, *QQ, *WKQ, *U, *R, *PH, *H;
    cudaGetSymbolAddress((void**)&X,   g_X);
    cudaGetSymbolAddress((void**)&QQ,  g_QQ);
    cudaGetSymbolAddress((void**)&WKQ, g_WKQ);
    cudaGetSymbolAddress((void**)&U,   g_U);
    cudaGetSymbolAddress((void**)&R,   g_R);
    cudaGetSymbolAddress((void**)&PH,  g_PH);
    cudaGetSymbolAddress((void**)&H,   g_H);

    const int FLASH_SMEM = 2 * G * VD * (int)sizeof(float);   // 48KB
    cudaFuncSetAttribute(flash_kernel,
                         cudaFuncAttributeMaxDynamicSharedMemorySize, FLASH_SMEM);

    dim3 blk(128);

    // biases into atomic-accumulated outputs
    init_kernel<<<(PAIRS * HID2 + 255) / 256, 256>>>(bqp, bvp, b1);
    // q = ques[:,:,0,:] @ Wqp^T + bqp -> X[:,512:]   (K=768, R=512, NT, niter=3)
    gemm_t2<false><<<dim3(8, 5, 8), blk>>>(ques, 32 * VD, Wqp, VD, X + HID, HID2, 3, 1.f);
    // qq = q @ Wq^T                                   (K=512, R=1024, NT, niter=2)
    gemm_t2<false><<<dim3(16, 5, 8), blk>>>(X + HID, HID2, Wq, HID, QQ, HID2, 2, 1.f);
    // wkq = Wk^T @ qq                                 (K=1024, R=512, TN, niter=4)
    gemm_t2<true ><<<dim3(8, 5, 8), blk>>>(QQ, HID2, Wk, HID, WKQ, HID, 4, 1.f);
    // u = Wvp^T @ wkq / sqrt(2H)                      (K=512, R=768, TN, niter=2)
    gemm_t2<true ><<<dim3(12, 5, 8), blk>>>(WKQ, HID, Wvp, VD, U, VD, 2, 1.f / 32.f);
    // flash: single HBM pass over video_enc (cp.async staged)
    flash_kernel<<<dim3(NCHUNK, PAIRS), 256, FLASH_SMEM>>>(video);
    combine_kernel<<<PAIRS, 256>>>();
    // pooled_h = r @ Wvp^T + bvp                       (K=768, R=512, NT, niter=3)
    gemm_t2<false><<<dim3(8, 5, 8), blk>>>(R, VD, Wvp, VD, PH, HID, 3, 1.f);
    // pooled_v = pooled_h @ Wv^T -> X[:, :512]         (K=512, R=512, NT, niter=2)
    gemm_t2<false><<<dim3(8, 5, 8), blk>>>(PH, HID, Wv, HID, X, HID2, 2, 1.f);
    // h = X @ W1^T + b1 (relu deferred)                (K=1024, R=512, NT, niter=4)
    gemm_t2<false><<<dim3(8, 5, 8), blk>>>(X, HID2, W1, HID2, H, HID, 4, 1.f);
    // out = softmax(relu(h) @ W2^T + b2 + output_mask)
    final_kernel<<<PAIRS, 32>>>(W2, b2, omask, out);
}